// round 7
// baseline (speedup 1.0000x reference)
#include <cuda_runtime.h>
#include <cstddef>

#define BATCHN 128
#define SEQN   2048
#define FEATN  64
#define UNITSN 64
#define GATESN 256
#define OUTDN  6
#define NT     384
#define NA     128

__device__ __forceinline__ float rcp_f(float x) {
    float r; asm("rcp.approx.f32 %0, %1;" : "=f"(r) : "f"(x)); return r;
}
__device__ __forceinline__ float ex2_f(float x) {
    float r; asm("ex2.approx.f32 %0, %1;" : "=f"(r) : "f"(x)); return r;
}

// Pipelined warp specialization, one CTA per batch element:
//   Group A (tid 0..127, 4 warps): layer-0 LSTM recurrence. Each thread owns
//     TWO gate columns (units uA and uA+32 of gate g); weights from smem
//     (k-quad layout: one LDS.128 = 4 consecutive k of one column).
//   Group D (tid 128..383, 8 warps): layers 1 AND 2 (shared W1/U1 held once
//     in registers, used twice), processing timestep t = s-1 (one slot behind A).
// One __syncthreads per slot + one D-scoped named barrier between layers 1/2.
// Lane map (both groups): uin = l&7, g = l>>3; unit's 4 gates live in lanes
// uin, uin+8, uin+16, uin+24 -> gather via shfl; lanes l<8 write h.
__global__ void __launch_bounds__(NT, 1)
lstm_pipe_kernel(const float* __restrict__ x,
                 const float* __restrict__ W0, const float* __restrict__ U0,
                 const float* __restrict__ b0,
                 const float* __restrict__ W1, const float* __restrict__ U1,
                 const float* __restrict__ b1,
                 const float* __restrict__ Wf, const float* __restrict__ bf,
                 const float* __restrict__ Wo, const float* __restrict__ bo,
                 float* __restrict__ out)
{
    extern __shared__ float sm[];
    float* W0q = sm;                      // 16384 floats, k-quad swizzled
    float* U0q = W0q + FEATN * GATESN;    // 16384
    float* h0s = U0q + FEATN * GATESN;    // 2*64 double buffered
    float* h1s = h0s + 2 * UNITSN;        // 2*64
    float* h2s = h1s + 2 * UNITSN;        // 2*64
    float* xs  = h2s + 2 * UNITSN;        // 2*64
    float* fs  = xs  + 2 * FEATN;         // 64

    const int b   = blockIdx.x;
    const int tid = threadIdx.x;
    const int l   = tid & 31;
    const int uin = l & 7;
    const int g   = l >> 3;
    const bool isA = (tid < NA);

    // Stage W0/U0 into k-quad swizzled layout: d = (k/4)*1024 + p*4 + (k%4),
    // p = u*4 + g (gate-interleaved column).
    for (int i = tid; i < FEATN * GATESN; i += NT) {
        int k  = i >> 8;
        int jj = i & 255;
        int pp = ((jj & 63) << 2) | (jj >> 6);
        int d  = ((k >> 2) << 10) + (pp << 2) + (k & 3);
        W0q[d] = W0[i];
        U0q[d] = U0[i];
    }

    // ---- D-group setup: full W1/U1 column in registers (one copy, 2 uses) ----
    const int wD = (tid - NA) >> 5;       // 0..7 (valid for D)
    const int uD = (wD << 3) | uin;       // 0..63
    const int jD = (g << 6) | uD;
    float w1r[64], u1r[64];
    float b1r = 0.f;
    if (!isA) {
#pragma unroll
        for (int k = 0; k < 64; k++) {
            w1r[k] = W1[(k << 8) + jD];
            u1r[k] = U1[(k << 8) + jD];
        }
        b1r = b1[jD];
    }

    // ---- A-group setup: two columns per thread ----
    const int wA = tid >> 5;              // 0..3 (valid for A)
    const int uA = (wA << 3) | uin;       // 0..31 ; second unit = uA+32
    const int pA = (uA << 2) | g;
    float b0A = 0.f, b0B = 0.f;
    if (isA) {
        b0A = b0[(g << 6) + uA];
        b0B = b0[(g << 6) + uA + 32];
    }

    if (tid < UNITSN) {
        h0s[tid] = 0.f; h0s[UNITSN + tid] = 0.f;
        h1s[tid] = 0.f; h1s[UNITSN + tid] = 0.f;
        h2s[tid] = 0.f; h2s[UNITSN + tid] = 0.f;
    }
    const float* xb = x + (size_t)b * SEQN * FEATN;
    if (tid < FEATN) xs[tid] = xb[tid];   // x(0) -> buffer 0

    const float kpre = (g == 2) ? -2.8853900817779268f : -1.4426950408889634f;
    const float kmul = (g == 2) ?  2.0f : 1.0f;
    const float kadd = (g == 2) ? -1.0f : 0.0f;
    const unsigned FULL = 0xffffffffu;

    float c0A = 0.f, c0B = 0.f;           // A cell state (units uA, uA+32)
    float c1 = 0.f, c2 = 0.f;             // D cell state (unit uD)
    __syncthreads();

    // Slots: s=0..SEQN. A computes h0(s) for s<SEQN; D computes layers 1,2 of
    // timestep t=s-1 for s>=1. h0(t) lives in h0s[((t&1)^1)] = h0s[s&1] for D.
    for (int s = 0; s <= SEQN; s++) {
        if (isA) {
            if (s < SEQN) {
                const int cb = s & 1, nb = cb ^ 1;
                float xn = 0.f;
                if (tid < FEATN) {
                    int tn = (s + 1 < SEQN) ? (s + 1) : s;
                    xn = __ldg(xb + (size_t)tn * FEATN + tid);
                }
                const float* xv = xs  + cb * FEATN;
                const float* hv = h0s + cb * UNITSN;
                const float* Wp = W0q + (pA << 2);
                const float* Up = U0q + (pA << 2);
                float aA0=0.f,aA1=0.f,aA2=0.f,aA3=0.f;
                float aB0=0.f,aB1=0.f,aB2=0.f,aB3=0.f;
#pragma unroll
                for (int q = 0; q < 16; q++) {
                    float4 xq  = *reinterpret_cast<const float4*>(xv + (q << 2));
                    float4 hq  = *reinterpret_cast<const float4*>(hv + (q << 2));
                    float4 wA4 = *reinterpret_cast<const float4*>(Wp + (q << 10));
                    float4 uA4 = *reinterpret_cast<const float4*>(Up + (q << 10));
                    float4 wB4 = *reinterpret_cast<const float4*>(Wp + (q << 10) + 512);
                    float4 uB4 = *reinterpret_cast<const float4*>(Up + (q << 10) + 512);
                    aA0 = fmaf(xq.x, wA4.x, aA0); aA1 = fmaf(xq.y, wA4.y, aA1);
                    aA2 = fmaf(xq.z, wA4.z, aA2); aA3 = fmaf(xq.w, wA4.w, aA3);
                    aA0 = fmaf(hq.x, uA4.x, aA0); aA1 = fmaf(hq.y, uA4.y, aA1);
                    aA2 = fmaf(hq.z, uA4.z, aA2); aA3 = fmaf(hq.w, uA4.w, aA3);
                    aB0 = fmaf(xq.x, wB4.x, aB0); aB1 = fmaf(xq.y, wB4.y, aB1);
                    aB2 = fmaf(xq.z, wB4.z, aB2); aB3 = fmaf(xq.w, wB4.w, aB3);
                    aB0 = fmaf(hq.x, uB4.x, aB0); aB1 = fmaf(hq.y, uB4.y, aB1);
                    aB2 = fmaf(hq.z, uB4.z, aB2); aB3 = fmaf(hq.w, uB4.w, aB3);
                }
                float zA = (aA0 + aA1) + (aA2 + aA3) + b0A;
                float zB = (aB0 + aB1) + (aB2 + aB3) + b0B;
                float actA = fmaf(rcp_f(1.0f + ex2_f(zA * kpre)), kmul, kadd);
                float actB = fmaf(rcp_f(1.0f + ex2_f(zB * kpre)), kmul, kadd);
                float viA = __shfl_sync(FULL, actA, uin);
                float vfA = __shfl_sync(FULL, actA, uin + 8);
                float vgA = __shfl_sync(FULL, actA, uin + 16);
                float voA = __shfl_sync(FULL, actA, uin + 24);
                float viB = __shfl_sync(FULL, actB, uin);
                float vfB = __shfl_sync(FULL, actB, uin + 8);
                float vgB = __shfl_sync(FULL, actB, uin + 16);
                float voB = __shfl_sync(FULL, actB, uin + 24);
                c0A = fmaf(vfA, c0A, viA * vgA);
                c0B = fmaf(vfB, c0B, viB * vgB);
                float hA = voA * fmaf(2.0f, rcp_f(1.0f + ex2_f(c0A * -2.8853900817779268f)), -1.0f);
                float hB = voB * fmaf(2.0f, rcp_f(1.0f + ex2_f(c0B * -2.8853900817779268f)), -1.0f);
                if (l < 8) {
                    h0s[nb * UNITSN + uA]      = hA;
                    h0s[nb * UNITSN + uA + 32] = hB;
                }
                if (tid < FEATN) xs[nb * FEATN + tid] = xn;
            }
        } else {
            if (s >= 1) {
                const int t  = s - 1;
                const int cb = t & 1, nb = cb ^ 1;
                const float* h0in = h0s + (s & 1) * UNITSN;   // h0(t)
                // ---------------- layer 1: h0(t)*W1 + h1(t-1)*U1 + b1 ----------------
                {
                    const float* hv = h1s + cb * UNITSN;
                    float a0=0.f,a1=0.f,a2=0.f,a3=0.f;
#pragma unroll
                    for (int q = 0; q < 16; q++) {
                        float4 iq = *reinterpret_cast<const float4*>(h0in + (q << 2));
                        float4 hq = *reinterpret_cast<const float4*>(hv   + (q << 2));
                        a0 = fmaf(iq.x, w1r[4*q+0], a0); a1 = fmaf(iq.y, w1r[4*q+1], a1);
                        a2 = fmaf(iq.z, w1r[4*q+2], a2); a3 = fmaf(iq.w, w1r[4*q+3], a3);
                        a0 = fmaf(hq.x, u1r[4*q+0], a0); a1 = fmaf(hq.y, u1r[4*q+1], a1);
                        a2 = fmaf(hq.z, u1r[4*q+2], a2); a3 = fmaf(hq.w, u1r[4*q+3], a3);
                    }
                    float z = (a0 + a1) + (a2 + a3) + b1r;
                    float act = fmaf(rcp_f(1.0f + ex2_f(z * kpre)), kmul, kadd);
                    float vi = __shfl_sync(FULL, act, uin);
                    float vf = __shfl_sync(FULL, act, uin + 8);
                    float vg = __shfl_sync(FULL, act, uin + 16);
                    float vo = __shfl_sync(FULL, act, uin + 24);
                    c1 = fmaf(vf, c1, vi * vg);
                    float hn = vo * fmaf(2.0f, rcp_f(1.0f + ex2_f(c1 * -2.8853900817779268f)), -1.0f);
                    if (l < 8) h1s[nb * UNITSN + uD] = hn;
                }
                asm volatile("bar.sync 1, 256;" ::: "memory");  // D-scoped
                // ------- layer 2: h1(t)*W1 + h2(t-1)*U1 + b1 (shared weights) -------
                {
                    const float* iv = h1s + nb * UNITSN;          // h1(t), just written
                    const float* hv = h2s + cb * UNITSN;
                    float a0=0.f,a1=0.f,a2=0.f,a3=0.f;
#pragma unroll
                    for (int q = 0; q < 16; q++) {
                        float4 iq = *reinterpret_cast<const float4*>(iv + (q << 2));
                        float4 hq = *reinterpret_cast<const float4*>(hv + (q << 2));
                        a0 = fmaf(iq.x, w1r[4*q+0], a0); a1 = fmaf(iq.y, w1r[4*q+1], a1);
                        a2 = fmaf(iq.z, w1r[4*q+2], a2); a3 = fmaf(iq.w, w1r[4*q+3], a3);
                        a0 = fmaf(hq.x, u1r[4*q+0], a0); a1 = fmaf(hq.y, u1r[4*q+1], a1);
                        a2 = fmaf(hq.z, u1r[4*q+2], a2); a3 = fmaf(hq.w, u1r[4*q+3], a3);
                    }
                    float z = (a0 + a1) + (a2 + a3) + b1r;
                    float act = fmaf(rcp_f(1.0f + ex2_f(z * kpre)), kmul, kadd);
                    float vi = __shfl_sync(FULL, act, uin);
                    float vf = __shfl_sync(FULL, act, uin + 8);
                    float vg = __shfl_sync(FULL, act, uin + 16);
                    float vo = __shfl_sync(FULL, act, uin + 24);
                    c2 = fmaf(vf, c2, vi * vg);
                    float hn = vo * fmaf(2.0f, rcp_f(1.0f + ex2_f(c2 * -2.8853900817779268f)), -1.0f);
                    if (l < 8) h2s[nb * UNITSN + uD] = hn;
                }
            }
        }
        __syncthreads();
    }

    // ---- dense head: relu(h2*Wf+bf) * Wo + bo ; final h2 in h2s[0..63] ----
    // (t=2047 wrote buffer ((2047&1)^1) = 0)
    if (tid < UNITSN) {
        float a = bf[tid];
#pragma unroll 8
        for (int k = 0; k < UNITSN; k++)
            a = fmaf(h2s[k], Wf[(k << 6) + tid], a);
        fs[tid] = fmaxf(a, 0.f);
    }
    __syncthreads();
    if (tid < OUTDN) {
        float a = bo[tid];
#pragma unroll 8
        for (int k = 0; k < UNITSN; k++)
            a = fmaf(fs[k], Wo[k * OUTDN + tid], a);
        out[b * OUTDN + tid] = a;
    }
}

extern "C" void kernel_launch(void* const* d_in, const int* in_sizes, int n_in,
                              void* d_out, int out_size)
{
    (void)in_sizes; (void)n_in; (void)out_size;
    const float* x  = (const float*)d_in[0];
    const float* W0 = (const float*)d_in[1];
    const float* U0 = (const float*)d_in[2];
    const float* b0 = (const float*)d_in[3];
    const float* W1 = (const float*)d_in[4];
    const float* U1 = (const float*)d_in[5];
    const float* b1 = (const float*)d_in[6];
    const float* Wf = (const float*)d_in[7];
    const float* bf = (const float*)d_in[8];
    const float* Wo = (const float*)d_in[9];
    const float* bo = (const float*)d_in[10];
    float* out = (float*)d_out;

    const size_t smem_bytes =
        (size_t)(2 * FEATN * GATESN + 6 * UNITSN + 2 * FEATN + UNITSN) * sizeof(float);
    cudaFuncSetAttribute(lstm_pipe_kernel,
                         cudaFuncAttributeMaxDynamicSharedMemorySize,
                         (int)smem_bytes);
    lstm_pipe_kernel<<<BATCHN, NT, smem_bytes>>>(x, W0, U0, b0, W1, U1, b1,
                                                 Wf, bf, Wo, bo, out);
}